// round 1
// baseline (speedup 1.0000x reference)
#include <cuda_runtime.h>
#include <math.h>

#define DEVF __device__ __forceinline__

// ---------------- problem constants ----------------
constexpr int HH = 512, WW = 512, NPIX = HH * WW, NC = 4;
constexpr int DBI = 5, DSP = 2;
constexpr int N_ITER = 10;

constexpr int BI_CAP = 1 << 22;          // hash capacity (power of 2), max keys 1.57M -> load 0.37
constexpr int SP_CAP = 1 << 21;
constexpr int BI_MMAX = NPIX * (DBI + 1); // 1,572,864 (hard upper bound on unique points)
constexpr int SP_MMAX = NPIX * (DSP + 1); //   786,432
constexpr unsigned long long KEMPTY = ~0ull;

// ---------------- device scratch (static, allocation-free) ----------------
__device__ unsigned long long g_bi_hk[BI_CAP];
__device__ unsigned long long g_sp_hk[SP_CAP];
__device__ int   g_bi_s2i[BI_CAP];
__device__ int   g_sp_s2i[SP_CAP];
__device__ unsigned long long g_bi_kl[BI_MMAX];
__device__ unsigned long long g_sp_kl[SP_MMAX];
__device__ int   g_bi_off[BI_MMAX];
__device__ int   g_sp_off[SP_MMAX];
__device__ float g_bi_ws[BI_MMAX];
__device__ float g_sp_ws[SP_MMAX];
// blur neighbors, axis-major: bn[(axis*MMAX + i)] = int2(n1, n2), -1 = missing
__device__ int   g_bi_bn[(DBI + 1) * BI_MMAX * 2];
__device__ int   g_sp_bn[(DSP + 1) * SP_MMAX * 2];
// ping-pong value buffers (C=4 for Q, C=1 for norm)
__device__ float g_bi_vA[BI_MMAX * NC];
__device__ float g_bi_vB[BI_MMAX * NC];
__device__ float g_sp_vA[SP_MMAX * NC];
__device__ float g_sp_vB[SP_MMAX * NC];
__device__ float g_bi_nA[BI_MMAX];
__device__ float g_bi_nB[BI_MMAX];
__device__ float g_sp_nA[SP_MMAX];
__device__ float g_sp_nB[SP_MMAX];
__device__ float g_bi_norm[NPIX];
__device__ float g_sp_norm[NPIX];
__device__ int   g_bi_cnt, g_sp_cnt;
__device__ float g_Q[NPIX * NC];

// ---------------- templated accessors ----------------
template<int D> DEVF unsigned long long* HK()  { return D == DBI ? g_bi_hk  : g_sp_hk;  }
template<int D> DEVF int*   S2I()  { return D == DBI ? g_bi_s2i : g_sp_s2i; }
template<int D> DEVF unsigned long long* KL()  { return D == DBI ? g_bi_kl  : g_sp_kl;  }
template<int D> DEVF int*   OFFA() { return D == DBI ? g_bi_off : g_sp_off; }
template<int D> DEVF float* WSA()  { return D == DBI ? g_bi_ws  : g_sp_ws;  }
template<int D> DEVF int*   BNA()  { return D == DBI ? g_bi_bn  : g_sp_bn;  }
template<int D> DEVF int*   CNT()  { return D == DBI ? &g_bi_cnt: &g_sp_cnt;}
template<int D> DEVF float* NORMA(){ return D == DBI ? g_bi_norm: g_sp_norm;}
template<int D> DEVF int    CAPC() { return D == DBI ? BI_CAP   : SP_CAP;   }
template<int D> DEVF int    MMAXC(){ return D == DBI ? BI_MMAX  : SP_MMAX;  }
template<int D, int C> DEVF float* BUF(int which) {
    if (C == 1) return D == DBI ? (which ? g_bi_nB : g_bi_nA) : (which ? g_sp_nB : g_sp_nA);
    return D == DBI ? (which ? g_bi_vB : g_bi_vA) : (which ? g_sp_vB : g_sp_vA);
}

// ---------------- hash ----------------
DEVF unsigned long long hmix(unsigned long long x) {
    x += 0x9E3779B97F4A7C15ull;
    x = (x ^ (x >> 30)) * 0xBF58476D1CE4E5B9ull;
    x = (x ^ (x >> 27)) * 0x94D049BB133111EBull;
    return x ^ (x >> 31);
}

template<int D>
DEVF int insert_slot(unsigned long long key) {
    const unsigned mask = (unsigned)(CAPC<D>() - 1);
    unsigned long long* hk = HK<D>();
    unsigned h = (unsigned)hmix(key) & mask;
    for (;;) {
        unsigned long long prev = atomicCAS(&hk[h], KEMPTY, key);
        if (prev == KEMPTY || prev == key) return (int)h;
        h = (h + 1) & mask;
    }
}

template<int D>
DEVF int find_id(unsigned long long key) {
    const unsigned mask = (unsigned)(CAPC<D>() - 1);
    unsigned long long* hk = HK<D>();
    unsigned h = (unsigned)hmix(key) & mask;
    for (;;) {
        unsigned long long k = hk[h];
        if (k == key) return S2I<D>()[h];
        if (k == KEMPTY) return -1;
        h = (h + 1) & mask;
    }
}

// ---------------- kernels ----------------
template<int D>
__global__ void k_reset() {
    int i = blockIdx.x * blockDim.x + threadIdx.x;
    if (i >= CAPC<D>()) return;
    HK<D>()[i] = KEMPTY;
    S2I<D>()[i] = -1;
    if (i == 0) *CNT<D>() = 0;
}

template<int D>
__global__ void k_build(const float* __restrict__ x) {
    int n = blockIdx.x * blockDim.x + threadIdx.x;
    if (n >= NPIX) return;
    int py = n / WW, px = n - py * WW;

    // features * scale  (replicating numpy fp32 arithmetic; no FMA contraction)
    float fs[D];
    const double inv_std = sqrt(2.0 / 3.0) * (D + 1);
#pragma unroll
    for (int j = 0; j < D; j++) {
        float f;
        if (D == DBI) {
            if (j == 0)      f = __fdiv_rn((float)px, 80.0f);
            else if (j == 1) f = __fdiv_rn((float)py, 80.0f);
            else             f = __fdiv_rn(x[n * 7 + (6 - j)], 0.0625f); // j=2->ch4, 3->ch3, 4->ch2
        } else {
            f = __fdiv_rn((float)(j == 0 ? px : py), 3.0f);
        }
        float sc = (float)(1.0 / sqrt((j + 2.0) * (j + 1.0)) * inv_std);
        fs[j] = __fmul_rn(f, sc);
    }

    // elevated = E @ fs   (E row structure of the permutohedral embedding)
    float elev[D + 1];
#pragma unroll
    for (int i = 0; i <= D; i++) {
        float s = 0.0f;
#pragma unroll
        for (int j = 0; j < D; j++) {
            float e = (i == 0) ? 1.0f : ((j == i - 1) ? -(float)i : (j >= i ? 1.0f : 0.0f));
            s = __fadd_rn(s, __fmul_rn(e, fs[j]));
        }
        elev[i] = s;
    }

    const float downf = __fdiv_rn(1.0f, (float)(D + 1));
    const float upf = (float)(D + 1);

    float rem0[D + 1], diff[D + 1];
    int   rnk[D + 1];
#pragma unroll
    for (int k = 0; k <= D; k++) {
        float v   = __fmul_rn(elev[k], downf);
        float upr = __fmul_rn(ceilf(v),  upf);
        float dnr = __fmul_rn(floorf(v), upf);
        rem0[k] = (__fsub_rn(upr, elev[k]) < __fsub_rn(elev[k], dnr)) ? upr : dnr;
    }
    float ssum = 0.0f;
#pragma unroll
    for (int k = 0; k <= D; k++) ssum = __fadd_rn(ssum, rem0[k]);
    int s = (int)__fmul_rn(ssum, downf);

#pragma unroll
    for (int k = 0; k <= D; k++) diff[k] = __fsub_rn(elev[k], rem0[k]);
#pragma unroll
    for (int k = 0; k <= D; k++) {
        int r = s;
#pragma unroll
        for (int j = 0; j <= D; j++) {
            if (j > k)      r += (diff[k] <  diff[j]);
            else if (j < k) r += (diff[j] >= diff[k]);
        }
        rnk[k] = r;
    }
#pragma unroll
    for (int k = 0; k <= D; k++) {
        if (rnk[k] < 0)      { rnk[k] += D + 1; rem0[k] = __fadd_rn(rem0[k], upf); }
        else if (rnk[k] > D) { rnk[k] -= D + 1; rem0[k] = __fsub_rn(rem0[k], upf); }
    }

    // barycentric weights
    float b[D + 2];
#pragma unroll
    for (int k = 0; k < D + 2; k++) b[k] = 0.0f;
#pragma unroll
    for (int k = 0; k <= D; k++) {
        float vs = __fmul_rn(__fsub_rn(elev[k], rem0[k]), downf);
        int idx = D - rnk[k];
        b[idx]     = __fadd_rn(b[idx], vs);
        b[idx + 1] = __fsub_rn(b[idx + 1], vs);
    }
    b[0] = __fadd_rn(b[0], __fadd_rn(1.0f, b[D + 1]));

    int remi[D + 1];
#pragma unroll
    for (int k = 0; k <= D; k++) remi[k] = (int)rem0[k];

    // keys + hash insert for each of the D+1 simplex vertices
#pragma unroll
    for (int m = 0; m <= D; m++) {
        unsigned long long key = 0ull;
#pragma unroll
        for (int j = 0; j < D; j++) {
            int r  = rnk[j];
            int cm = (r < D + 1 - m) ? m : m - (D + 1);
            int c  = remi[j] + cm;
            key |= ((unsigned long long)((unsigned)(c + 2048) & 0xFFFu)) << (12 * j);
        }
        int slot = insert_slot<D>(key);
        OFFA<D>()[n * (D + 1) + m] = slot;   // temporarily a slot; fixed after compaction
        WSA<D>()[n * (D + 1) + m]  = b[m];
    }
}

template<int D>
__global__ void k_compact() {
    int i = blockIdx.x * blockDim.x + threadIdx.x;
    if (i >= CAPC<D>()) return;
    unsigned long long k = HK<D>()[i];
    if (k != KEMPTY) {
        int id = atomicAdd(CNT<D>(), 1);
        S2I<D>()[i] = id;
        KL<D>()[id] = k;
    }
}

template<int D>
__global__ void k_fixoff() {
    int i = blockIdx.x * blockDim.x + threadIdx.x;
    if (i >= NPIX * (D + 1)) return;
    OFFA<D>()[i] = S2I<D>()[OFFA<D>()[i]];
}

template<int D>
__global__ void k_neigh() {
    int i = blockIdx.x * blockDim.x + threadIdx.x;
    if (i >= *CNT<D>()) return;
    unsigned long long key = KL<D>()[i];
    int c[D];
#pragma unroll
    for (int j = 0; j < D; j++) c[j] = (int)((key >> (12 * j)) & 0xFFFu) - 2048;
#pragma unroll
    for (int j = 0; j <= D; j++) {
        unsigned long long k1 = 0ull, k2 = 0ull;
#pragma unroll
        for (int t = 0; t < D; t++) {
            int add = (j < D && t == j) ? (D + 1) : 0;
            int c1 = c[t] - 1 + add;
            int c2 = c[t] + 1 - add;
            k1 |= ((unsigned long long)((unsigned)(c1 + 2048) & 0xFFFu)) << (12 * t);
            k2 |= ((unsigned long long)((unsigned)(c2 + 2048) & 0xFFFu)) << (12 * t);
        }
        ((int2*)BNA<D>())[j * MMAXC<D>() + i] = make_int2(find_id<D>(k1), find_id<D>(k2));
    }
}

template<int D, int C>
__global__ void k_clear() {
    int i = blockIdx.x * blockDim.x + threadIdx.x;
    if (i >= (*CNT<D>()) * C) return;
    BUF<D, C>(0)[i] = 0.0f;
}

template<int D>
__global__ void k_splatN() {
    int i = blockIdx.x * blockDim.x + threadIdx.x;
    if (i >= NPIX * (D + 1)) return;
    atomicAdd(&BUF<D, 1>(0)[OFFA<D>()[i]], WSA<D>()[i]);
}

template<int D>
__global__ void k_splatQ() {
    int n = blockIdx.x * blockDim.x + threadIdx.x;
    if (n >= NPIX) return;
    float4 q = ((const float4*)g_Q)[n];
    float* v = BUF<D, NC>(0);
#pragma unroll
    for (int m = 0; m <= D; m++) {
        int id  = OFFA<D>()[n * (D + 1) + m];
        float w = WSA<D>()[n * (D + 1) + m];
        atomicAdd(&v[id * 4 + 0], w * q.x);
        atomicAdd(&v[id * 4 + 1], w * q.y);
        atomicAdd(&v[id * 4 + 2], w * q.z);
        atomicAdd(&v[id * 4 + 3], w * q.w);
    }
}

template<int D, int C>
__global__ void k_blur(int axis, int parity) {
    int i = blockIdx.x * blockDim.x + threadIdx.x;
    if (i >= *CNT<D>()) return;
    const float* in = BUF<D, C>(parity);
    float* outp     = BUF<D, C>(parity ^ 1);
    int2 nb = ((const int2*)BNA<D>())[axis * MMAXC<D>() + i];
    if (C == 1) {
        float s = 0.0f;
        if (nb.x >= 0) s += in[nb.x];
        if (nb.y >= 0) s += in[nb.y];
        outp[i] = in[i] + 0.5f * s;
    } else {
        float4 v = ((const float4*)in)[i];
        float sx = 0, sy = 0, sz = 0, sw = 0;
        if (nb.x >= 0) { float4 a = ((const float4*)in)[nb.x]; sx += a.x; sy += a.y; sz += a.z; sw += a.w; }
        if (nb.y >= 0) { float4 a = ((const float4*)in)[nb.y]; sx += a.x; sy += a.y; sz += a.z; sw += a.w; }
        v.x += 0.5f * sx; v.y += 0.5f * sy; v.z += 0.5f * sz; v.w += 0.5f * sw;
        ((float4*)outp)[i] = v;
    }
}

template<int D>
__global__ void k_sliceN() {
    int n = blockIdx.x * blockDim.x + threadIdx.x;
    if (n >= NPIX) return;
    const float* v = BUF<D, 1>((D + 1) & 1);  // final ping-pong buffer after D+1 passes
    float s = 0.0f;
#pragma unroll
    for (int m = 0; m <= D; m++) {
        int id = OFFA<D>()[n * (D + 1) + m];
        s += WSA<D>()[n * (D + 1) + m] * v[id];
    }
    NORMA<D>()[n] = s * (D == DBI ? (32.0f / 33.0f) : 0.8f);
}

__global__ void k_initQ(const float* __restrict__ logits) {
    int n = blockIdx.x * blockDim.x + threadIdx.x;
    if (n >= NPIX) return;
    float4 lg = ((const float4*)logits)[n];
    float a[4] = { lg.x, lg.y, lg.z, lg.w };
    float mx = fmaxf(fmaxf(a[0], a[1]), fmaxf(a[2], a[3]));
    float e0 = expf(a[0] - mx), e1 = expf(a[1] - mx), e2 = expf(a[2] - mx), e3 = expf(a[3] - mx);
    float inv = 1.0f / (e0 + e1 + e2 + e3);
    ((float4*)g_Q)[n] = make_float4(e0 * inv, e1 * inv, e2 * inv, e3 * inv);
}

__global__ void k_update(const float* __restrict__ logits) {
    int n = blockIdx.x * blockDim.x + threadIdx.x;
    if (n >= NPIX) return;
    const float4* vb = (const float4*)BUF<DBI, NC>((DBI + 1) & 1); // bi: 6 passes -> buffer A
    const float4* vs = (const float4*)BUF<DSP, NC>((DSP + 1) & 1); // sp: 3 passes -> buffer B
    float ab[4] = {0, 0, 0, 0}, as[4] = {0, 0, 0, 0};
#pragma unroll
    for (int m = 0; m <= DBI; m++) {
        int id  = g_bi_off[n * (DBI + 1) + m];
        float w = g_bi_ws[n * (DBI + 1) + m];
        float4 t = vb[id];
        ab[0] += w * t.x; ab[1] += w * t.y; ab[2] += w * t.z; ab[3] += w * t.w;
    }
#pragma unroll
    for (int m = 0; m <= DSP; m++) {
        int id  = g_sp_off[n * (DSP + 1) + m];
        float w = g_sp_ws[n * (DSP + 1) + m];
        float4 t = vs[id];
        as[0] += w * t.x; as[1] += w * t.y; as[2] += w * t.z; as[3] += w * t.w;
    }
    float fbi = 10.0f * (32.0f / 33.0f) / (g_bi_norm[n] + 1e-20f);
    float fsp = 3.0f * 0.8f / (g_sp_norm[n] + 1e-20f);
    float4 lg = ((const float4*)logits)[n];
    float lga[4] = { lg.x, lg.y, lg.z, lg.w };
    float a[4];
    float mx = -1e30f;
#pragma unroll
    for (int c = 0; c < 4; c++) {
        a[c] = lga[c] + fbi * ab[c] + fsp * as[c];
        mx = fmaxf(mx, a[c]);
    }
    float e[4], ssum = 0.0f;
#pragma unroll
    for (int c = 0; c < 4; c++) { e[c] = expf(a[c] - mx); ssum += e[c]; }
    float inv = 1.0f / ssum;
    ((float4*)g_Q)[n] = make_float4(e[0] * inv, e[1] * inv, e[2] * inv, e[3] * inv);
}

__global__ void k_out(float* __restrict__ out) {
    int i = blockIdx.x * blockDim.x + threadIdx.x;
    if (i >= NPIX * NC) return;
    out[i] = g_Q[i];
}

// ---------------- launch ----------------
extern "C" void kernel_launch(void* const* d_in, const int* in_sizes, int n_in,
                              void* d_out, int out_size) {
    (void)in_sizes; (void)n_in; (void)out_size;
    const float* x      = (const float*)d_in[0];
    const float* logits = (const float*)d_in[1];
    float* out = (float*)d_out;

    const int B = 256;
    auto g = [](long n) { return (unsigned)((n + 255) / 256); };

    // ---- lattice construction ----
    k_reset<DBI><<<g(BI_CAP), B>>>();
    k_reset<DSP><<<g(SP_CAP), B>>>();
    k_build<DBI><<<g(NPIX), B>>>(x);
    k_build<DSP><<<g(NPIX), B>>>(x);
    k_compact<DBI><<<g(BI_CAP), B>>>();
    k_compact<DSP><<<g(SP_CAP), B>>>();
    k_fixoff<DBI><<<g(BI_MMAX), B>>>();
    k_fixoff<DSP><<<g(SP_MMAX), B>>>();
    k_neigh<DBI><<<g(BI_MMAX), B>>>();
    k_neigh<DSP><<<g(SP_MMAX), B>>>();

    // ---- normalization filters (ones) ----
    k_clear<DBI, 1><<<g(BI_MMAX), B>>>();
    k_splatN<DBI><<<g(BI_MMAX), B>>>();
    for (int j = 0; j <= DBI; j++) k_blur<DBI, 1><<<g(BI_MMAX), B>>>(j, j & 1);
    k_sliceN<DBI><<<g(NPIX), B>>>();

    k_clear<DSP, 1><<<g(SP_MMAX), B>>>();
    k_splatN<DSP><<<g(SP_MMAX), B>>>();
    for (int j = 0; j <= DSP; j++) k_blur<DSP, 1><<<g(SP_MMAX), B>>>(j, j & 1);
    k_sliceN<DSP><<<g(NPIX), B>>>();

    // ---- mean-field iterations ----
    k_initQ<<<g(NPIX), B>>>(logits);
    for (int it = 0; it < N_ITER; it++) {
        k_clear<DBI, NC><<<g((long)BI_MMAX * NC), B>>>();
        k_splatQ<DBI><<<g(NPIX), B>>>();
        for (int j = 0; j <= DBI; j++) k_blur<DBI, NC><<<g(BI_MMAX), B>>>(j, j & 1);

        k_clear<DSP, NC><<<g((long)SP_MMAX * NC), B>>>();
        k_splatQ<DSP><<<g(NPIX), B>>>();
        for (int j = 0; j <= DSP; j++) k_blur<DSP, NC><<<g(SP_MMAX), B>>>(j, j & 1);

        k_update<<<g(NPIX), B>>>(logits);
    }
    k_out<<<g((long)NPIX * NC), B>>>(out);
}

// round 2
// speedup vs baseline: 1.4747x; 1.4747x over previous
#include <cuda_runtime.h>
#include <math.h>

#define DEVF __device__ __forceinline__

// ---------------- problem constants ----------------
constexpr int HH = 512, WW = 512, NPIX = HH * WW, NC = 4;
constexpr int DBI = 5, DSP = 2;
constexpr int N_ITER = 10;

constexpr int BI_CAP = 1 << 22;
constexpr int SP_CAP = 1 << 21;
constexpr int BI_MMAX = NPIX * (DBI + 1); // 1,572,864
constexpr int SP_MMAX = NPIX * (DSP + 1); //   786,432
constexpr unsigned long long KEMPTY = ~0ull;

// ---------------- device scratch ----------------
__device__ unsigned long long g_bi_hk[BI_CAP];
__device__ unsigned long long g_sp_hk[SP_CAP];
__device__ int   g_bi_s2i[BI_CAP];
__device__ int   g_sp_s2i[SP_CAP];
__device__ unsigned long long g_bi_kl[BI_MMAX];
__device__ unsigned long long g_sp_kl[SP_MMAX];
__device__ int   g_bi_off[BI_MMAX];
__device__ int   g_sp_off[SP_MMAX];
__device__ float g_bi_ws[BI_MMAX];
__device__ float g_sp_ws[SP_MMAX];
__device__ int   g_bi_bn[(DBI + 1) * BI_MMAX * 2];
__device__ int   g_sp_bn[(DSP + 1) * SP_MMAX * 2];
// value buffers: A(0), B(1) ping-pong; C(2) = splat target
__device__ float g_bi_vA[BI_MMAX * NC];
__device__ float g_bi_vB[BI_MMAX * NC];
__device__ float g_bi_vC[BI_MMAX * NC];
__device__ float g_sp_vA[SP_MMAX * NC];
__device__ float g_sp_vB[SP_MMAX * NC];
__device__ float g_sp_vC[SP_MMAX * NC];
__device__ float g_bi_nA[BI_MMAX];
__device__ float g_bi_nB[BI_MMAX];
__device__ float g_sp_nA[SP_MMAX];
__device__ float g_sp_nB[SP_MMAX];
__device__ float g_bi_norm[NPIX];
__device__ float g_sp_norm[NPIX];
__device__ int   g_bi_cnt, g_sp_cnt;

// ---------------- templated accessors ----------------
template<int D> DEVF unsigned long long* HK()  { return D == DBI ? g_bi_hk  : g_sp_hk;  }
template<int D> DEVF int*   S2I()  { return D == DBI ? g_bi_s2i : g_sp_s2i; }
template<int D> DEVF unsigned long long* KL()  { return D == DBI ? g_bi_kl  : g_sp_kl;  }
template<int D> DEVF int*   OFFA() { return D == DBI ? g_bi_off : g_sp_off; }
template<int D> DEVF float* WSA()  { return D == DBI ? g_bi_ws  : g_sp_ws;  }
template<int D> DEVF int*   BNA()  { return D == DBI ? g_bi_bn  : g_sp_bn;  }
template<int D> DEVF int*   CNT()  { return D == DBI ? &g_bi_cnt: &g_sp_cnt;}
template<int D> DEVF int    CAPC() { return D == DBI ? BI_CAP   : SP_CAP;   }
template<int D> DEVF int    MMAXC(){ return D == DBI ? BI_MMAX  : SP_MMAX;  }
template<int D, int C> DEVF float* BUF3(int which) {
    if (C == 1) return D == DBI ? (which ? g_bi_nB : g_bi_nA) : (which ? g_sp_nB : g_sp_nA);
    if (D == DBI) return which == 2 ? g_bi_vC : (which ? g_bi_vB : g_bi_vA);
    return which == 2 ? g_sp_vC : (which ? g_sp_vB : g_sp_vA);
}

// vectorized float4 reduction (sm_90+)
DEVF void red4(float* p, float a, float b, float c, float d) {
    asm volatile("{ .reg .u64 pg; cvta.to.global.u64 pg, %0; "
                 "red.global.add.v4.f32 [pg], {%1,%2,%3,%4}; }"
                 :: "l"(p), "f"(a), "f"(b), "f"(c), "f"(d) : "memory");
}

// ---------------- hash ----------------
DEVF unsigned long long hmix(unsigned long long x) {
    x += 0x9E3779B97F4A7C15ull;
    x = (x ^ (x >> 30)) * 0xBF58476D1CE4E5B9ull;
    x = (x ^ (x >> 27)) * 0x94D049BB133111EBull;
    return x ^ (x >> 31);
}

template<int D>
DEVF int insert_slot(unsigned long long key) {
    const unsigned mask = (unsigned)(CAPC<D>() - 1);
    unsigned long long* hk = HK<D>();
    unsigned h = (unsigned)hmix(key) & mask;
    for (;;) {
        unsigned long long prev = atomicCAS(&hk[h], KEMPTY, key);
        if (prev == KEMPTY || prev == key) return (int)h;
        h = (h + 1) & mask;
    }
}

template<int D>
DEVF int find_id(unsigned long long key) {
    const unsigned mask = (unsigned)(CAPC<D>() - 1);
    unsigned long long* hk = HK<D>();
    unsigned h = (unsigned)hmix(key) & mask;
    for (;;) {
        unsigned long long k = hk[h];
        if (k == key) return S2I<D>()[h];
        if (k == KEMPTY) return -1;
        h = (h + 1) & mask;
    }
}

// ---------------- kernels ----------------
template<int D>
__global__ void k_reset() {
    int i = blockIdx.x * blockDim.x + threadIdx.x;
    if (i >= CAPC<D>()) return;
    HK<D>()[i] = KEMPTY;
    S2I<D>()[i] = -1;
    if (i == 0) *CNT<D>() = 0;
}

template<int D>
__global__ void k_build(const float* __restrict__ x) {
    int n = blockIdx.x * blockDim.x + threadIdx.x;
    if (n >= NPIX) return;
    int py = n / WW, px = n - py * WW;

    float fs[D];
    const double inv_std = sqrt(2.0 / 3.0) * (D + 1);
#pragma unroll
    for (int j = 0; j < D; j++) {
        float f;
        if (D == DBI) {
            if (j == 0)      f = __fdiv_rn((float)px, 80.0f);
            else if (j == 1) f = __fdiv_rn((float)py, 80.0f);
            else             f = __fdiv_rn(x[n * 7 + (6 - j)], 0.0625f);
        } else {
            f = __fdiv_rn((float)(j == 0 ? px : py), 3.0f);
        }
        float sc = (float)(1.0 / sqrt((j + 2.0) * (j + 1.0)) * inv_std);
        fs[j] = __fmul_rn(f, sc);
    }

    float elev[D + 1];
#pragma unroll
    for (int i = 0; i <= D; i++) {
        float s = 0.0f;
#pragma unroll
        for (int j = 0; j < D; j++) {
            float e = (i == 0) ? 1.0f : ((j == i - 1) ? -(float)i : (j >= i ? 1.0f : 0.0f));
            s = __fadd_rn(s, __fmul_rn(e, fs[j]));
        }
        elev[i] = s;
    }

    const float downf = __fdiv_rn(1.0f, (float)(D + 1));
    const float upf = (float)(D + 1);

    float rem0[D + 1], diff[D + 1];
    int   rnk[D + 1];
#pragma unroll
    for (int k = 0; k <= D; k++) {
        float v   = __fmul_rn(elev[k], downf);
        float upr = __fmul_rn(ceilf(v),  upf);
        float dnr = __fmul_rn(floorf(v), upf);
        rem0[k] = (__fsub_rn(upr, elev[k]) < __fsub_rn(elev[k], dnr)) ? upr : dnr;
    }
    float ssum = 0.0f;
#pragma unroll
    for (int k = 0; k <= D; k++) ssum = __fadd_rn(ssum, rem0[k]);
    int s = (int)__fmul_rn(ssum, downf);

#pragma unroll
    for (int k = 0; k <= D; k++) diff[k] = __fsub_rn(elev[k], rem0[k]);
#pragma unroll
    for (int k = 0; k <= D; k++) {
        int r = s;
#pragma unroll
        for (int j = 0; j <= D; j++) {
            if (j > k)      r += (diff[k] <  diff[j]);
            else if (j < k) r += (diff[j] >= diff[k]);
        }
        rnk[k] = r;
    }
#pragma unroll
    for (int k = 0; k <= D; k++) {
        if (rnk[k] < 0)      { rnk[k] += D + 1; rem0[k] = __fadd_rn(rem0[k], upf); }
        else if (rnk[k] > D) { rnk[k] -= D + 1; rem0[k] = __fsub_rn(rem0[k], upf); }
    }

    float b[D + 2];
#pragma unroll
    for (int k = 0; k < D + 2; k++) b[k] = 0.0f;
#pragma unroll
    for (int k = 0; k <= D; k++) {
        float vs = __fmul_rn(__fsub_rn(elev[k], rem0[k]), downf);
        int idx = D - rnk[k];
        b[idx]     = __fadd_rn(b[idx], vs);
        b[idx + 1] = __fsub_rn(b[idx + 1], vs);
    }
    b[0] = __fadd_rn(b[0], __fadd_rn(1.0f, b[D + 1]));

    int remi[D + 1];
#pragma unroll
    for (int k = 0; k <= D; k++) remi[k] = (int)rem0[k];

#pragma unroll
    for (int m = 0; m <= D; m++) {
        unsigned long long key = 0ull;
#pragma unroll
        for (int j = 0; j < D; j++) {
            int r  = rnk[j];
            int cm = (r < D + 1 - m) ? m : m - (D + 1);
            int c  = remi[j] + cm;
            key |= ((unsigned long long)((unsigned)(c + 2048) & 0xFFFu)) << (12 * j);
        }
        int slot = insert_slot<D>(key);
        OFFA<D>()[n * (D + 1) + m] = slot;
        WSA<D>()[n * (D + 1) + m]  = b[m];
    }
}

template<int D>
__global__ void k_compact() {
    int i = blockIdx.x * blockDim.x + threadIdx.x;
    if (i >= CAPC<D>()) return;
    unsigned long long k = HK<D>()[i];
    if (k != KEMPTY) {
        int id = atomicAdd(CNT<D>(), 1);
        S2I<D>()[i] = id;
        KL<D>()[id] = k;
    }
}

template<int D>
__global__ void k_fixoff() {
    int i = blockIdx.x * blockDim.x + threadIdx.x;
    if (i >= NPIX * (D + 1)) return;
    OFFA<D>()[i] = S2I<D>()[OFFA<D>()[i]];
}

template<int D>
__global__ void k_neigh() {
    int i = blockIdx.x * blockDim.x + threadIdx.x;
    if (i >= *CNT<D>()) return;
    unsigned long long key = KL<D>()[i];
    int c[D];
#pragma unroll
    for (int j = 0; j < D; j++) c[j] = (int)((key >> (12 * j)) & 0xFFFu) - 2048;
#pragma unroll
    for (int j = 0; j <= D; j++) {
        unsigned long long k1 = 0ull, k2 = 0ull;
#pragma unroll
        for (int t = 0; t < D; t++) {
            int add = (j < D && t == j) ? (D + 1) : 0;
            int c1 = c[t] - 1 + add;
            int c2 = c[t] + 1 - add;
            k1 |= ((unsigned long long)((unsigned)(c1 + 2048) & 0xFFFu)) << (12 * t);
            k2 |= ((unsigned long long)((unsigned)(c2 + 2048) & 0xFFFu)) << (12 * t);
        }
        ((int2*)BNA<D>())[j * MMAXC<D>() + i] = make_int2(find_id<D>(k1), find_id<D>(k2));
    }
}

// clear norm splat buffers (nA for both lattices)
__global__ void k_clearN() {
    int i = blockIdx.x * blockDim.x + threadIdx.x;
    if (i < BI_MMAX) { if (i < g_bi_cnt) g_bi_nA[i] = 0.0f; }
    else { int k = i - BI_MMAX; if (k < g_sp_cnt) g_sp_nA[k] = 0.0f; }
}

// clear splat (C) buffers for both lattices
__global__ void k_clearC() {
    int i = blockIdx.x * blockDim.x + threadIdx.x;
    if (i < BI_MMAX * NC) { if (i < g_bi_cnt * NC) g_bi_vC[i] = 0.0f; }
    else { int k = i - BI_MMAX * NC; if (k < g_sp_cnt * NC) g_sp_vC[k] = 0.0f; }
}

// norm splat: both lattices in one kernel
__global__ void k_splatN() {
    int i = blockIdx.x * blockDim.x + threadIdx.x;
    if (i < BI_MMAX) atomicAdd(&g_bi_nA[g_bi_off[i]], g_bi_ws[i]);
    else { int k = i - BI_MMAX; if (k < SP_MMAX) atomicAdd(&g_sp_nA[g_sp_off[k]], g_sp_ws[k]); }
}

template<int D, int C>
DEVF void blur_one(int i, int axis, const float* __restrict__ in, float* __restrict__ outp) {
    int2 nb = ((const int2*)BNA<D>())[axis * MMAXC<D>() + i];
    if (C == 1) {
        float s = 0.0f;
        if (nb.x >= 0) s += in[nb.x];
        if (nb.y >= 0) s += in[nb.y];
        outp[i] = in[i] + 0.5f * s;
    } else {
        float4 v = ((const float4*)in)[i];
        float sx = 0, sy = 0, sz = 0, sw = 0;
        if (nb.x >= 0) { float4 a = ((const float4*)in)[nb.x]; sx += a.x; sy += a.y; sz += a.z; sw += a.w; }
        if (nb.y >= 0) { float4 a = ((const float4*)in)[nb.y]; sx += a.x; sy += a.y; sz += a.z; sw += a.w; }
        v.x += 0.5f * sx; v.y += 0.5f * sy; v.z += 0.5f * sz; v.w += 0.5f * sw;
        ((float4*)outp)[i] = v;
    }
}

// combined blur: handles bi (always) + sp (when axis <= DSP, grid large enough)
template<int C>
__global__ void k_blur(int axis, int inb, int outb) {
    int i = blockIdx.x * blockDim.x + threadIdx.x;
    if (i < BI_MMAX) {
        if (i < g_bi_cnt)
            blur_one<DBI, C>(i, axis, BUF3<DBI, C>(inb), BUF3<DBI, C>(outb));
    } else {
        int k = i - BI_MMAX;
        if (k < g_sp_cnt)
            blur_one<DSP, C>(k, axis, BUF3<DSP, C>(inb), BUF3<DSP, C>(outb));
    }
}

// slice of norm filters (bi final in nA, sp final in nB)
__global__ void k_sliceN() {
    int n = blockIdx.x * blockDim.x + threadIdx.x;
    if (n >= NPIX) return;
    float sb = 0.0f, ss = 0.0f;
#pragma unroll
    for (int m = 0; m <= DBI; m++)
        sb += g_bi_ws[n * (DBI + 1) + m] * g_bi_nA[g_bi_off[n * (DBI + 1) + m]];
#pragma unroll
    for (int m = 0; m <= DSP; m++)
        ss += g_sp_ws[n * (DSP + 1) + m] * g_sp_nB[g_sp_off[n * (DSP + 1) + m]];
    g_bi_norm[n] = sb * (32.0f / 33.0f);
    g_sp_norm[n] = ss * 0.8f;
}

DEVF void splat_q(int n, float q0, float q1, float q2, float q3) {
#pragma unroll
    for (int m = 0; m <= DBI; m++) {
        int id  = g_bi_off[n * (DBI + 1) + m];
        float w = g_bi_ws[n * (DBI + 1) + m];
        red4(&g_bi_vC[id * 4], w * q0, w * q1, w * q2, w * q3);
    }
#pragma unroll
    for (int m = 0; m <= DSP; m++) {
        int id  = g_sp_off[n * (DSP + 1) + m];
        float w = g_sp_ws[n * (DSP + 1) + m];
        red4(&g_sp_vC[id * 4], w * q0, w * q1, w * q2, w * q3);
    }
}

// initial Q = softmax(logits), splat directly into C buffers
__global__ void k_initQ(const float* __restrict__ logits) {
    int n = blockIdx.x * blockDim.x + threadIdx.x;
    if (n >= NPIX) return;
    float4 lg = ((const float4*)logits)[n];
    float mx = fmaxf(fmaxf(lg.x, lg.y), fmaxf(lg.z, lg.w));
    float e0 = expf(lg.x - mx), e1 = expf(lg.y - mx), e2 = expf(lg.z - mx), e3 = expf(lg.w - mx);
    float inv = 1.0f / (e0 + e1 + e2 + e3);
    splat_q(n, e0 * inv, e1 * inv, e2 * inv, e3 * inv);
}

// mean-field update: slice blurred filters, softmax, then either splat (next iter) or write out
template<bool LAST>
__global__ void k_update(const float* __restrict__ logits, float* __restrict__ out) {
    int n = blockIdx.x * blockDim.x + threadIdx.x;
    if (n >= NPIX) return;
    const float4* vb = (const float4*)g_bi_vA; // bi after 6 passes (C->B->A->B->A->B->A)
    const float4* vs = (const float4*)g_sp_vB; // sp after 3 passes (C->B->A->B)
    float ab0 = 0, ab1 = 0, ab2 = 0, ab3 = 0;
    float as0 = 0, as1 = 0, as2 = 0, as3 = 0;
#pragma unroll
    for (int m = 0; m <= DBI; m++) {
        int id  = g_bi_off[n * (DBI + 1) + m];
        float w = g_bi_ws[n * (DBI + 1) + m];
        float4 t = vb[id];
        ab0 += w * t.x; ab1 += w * t.y; ab2 += w * t.z; ab3 += w * t.w;
    }
#pragma unroll
    for (int m = 0; m <= DSP; m++) {
        int id  = g_sp_off[n * (DSP + 1) + m];
        float w = g_sp_ws[n * (DSP + 1) + m];
        float4 t = vs[id];
        as0 += w * t.x; as1 += w * t.y; as2 += w * t.z; as3 += w * t.w;
    }
    float fbi = 10.0f * (32.0f / 33.0f) / (g_bi_norm[n] + 1e-20f);
    float fsp = 3.0f * 0.8f / (g_sp_norm[n] + 1e-20f);
    float4 lg = ((const float4*)logits)[n];
    float a0 = lg.x + fbi * ab0 + fsp * as0;
    float a1 = lg.y + fbi * ab1 + fsp * as1;
    float a2 = lg.z + fbi * ab2 + fsp * as2;
    float a3 = lg.w + fbi * ab3 + fsp * as3;
    float mx = fmaxf(fmaxf(a0, a1), fmaxf(a2, a3));
    float e0 = expf(a0 - mx), e1 = expf(a1 - mx), e2 = expf(a2 - mx), e3 = expf(a3 - mx);
    float inv = 1.0f / (e0 + e1 + e2 + e3);
    float q0 = e0 * inv, q1 = e1 * inv, q2 = e2 * inv, q3 = e3 * inv;
    if (LAST) {
        ((float4*)out)[n] = make_float4(q0, q1, q2, q3);
    } else {
        splat_q(n, q0, q1, q2, q3);
    }
}

// ---------------- launch ----------------
extern "C" void kernel_launch(void* const* d_in, const int* in_sizes, int n_in,
                              void* d_out, int out_size) {
    (void)in_sizes; (void)n_in; (void)out_size;
    const float* x      = (const float*)d_in[0];
    const float* logits = (const float*)d_in[1];
    float* out = (float*)d_out;

    const int B = 256;
    auto g = [](long n) { return (unsigned)((n + 255) / 256); };
    const unsigned G_BOTH  = g(BI_MMAX + SP_MMAX);
    const unsigned G_BI    = g(BI_MMAX);
    const unsigned G_BOTHC = g((long)(BI_MMAX + SP_MMAX) * NC);
    const unsigned G_PIX   = g(NPIX);

    // ---- lattice construction ----
    k_reset<DBI><<<g(BI_CAP), B>>>();
    k_reset<DSP><<<g(SP_CAP), B>>>();
    k_build<DBI><<<G_PIX, B>>>(x);
    k_build<DSP><<<G_PIX, B>>>(x);
    k_compact<DBI><<<g(BI_CAP), B>>>();
    k_compact<DSP><<<g(SP_CAP), B>>>();
    k_fixoff<DBI><<<G_BI, B>>>();
    k_fixoff<DSP><<<g(SP_MMAX), B>>>();
    k_neigh<DBI><<<G_BI, B>>>();
    k_neigh<DSP><<<g(SP_MMAX), B>>>();

    // ---- normalization filters ----
    k_clearN<<<G_BOTH, B>>>();
    k_splatN<<<G_BOTH, B>>>();
    // norm blur: splat in A; pass j: in = j&1, out = (j&1)^1
    for (int j = 0; j <= DBI; j++) {
        unsigned grd = (j <= DSP) ? G_BOTH : G_BI;
        k_blur<1><<<grd, B>>>(j, j & 1, (j & 1) ^ 1);
    }
    k_sliceN<<<G_PIX, B>>>();

    // ---- mean-field iterations ----
    k_clearC<<<G_BOTHC, B>>>();
    k_initQ<<<G_PIX, B>>>(logits);
    for (int it = 0; it < N_ITER; it++) {
        // blur passes: pass 0 reads C(2) -> B(1); then B->A->B->...
        for (int j = 0; j <= DBI; j++) {
            int inb  = (j == 0) ? 2 : (j & 1);
            int outb = (j & 1) ^ 1;
            unsigned grd = (j <= DSP) ? G_BOTH : G_BI;
            k_blur<NC><<<grd, B>>>(j, inb, outb);
            if (j == 0 && it != N_ITER - 1) k_clearC<<<G_BOTHC, B>>>();
        }
        if (it == N_ITER - 1)
            k_update<true><<<G_PIX, B>>>(logits, out);
        else
            k_update<false><<<G_PIX, B>>>(logits, out);
    }
}

// round 3
// speedup vs baseline: 2.0349x; 1.3799x over previous
#include <cuda_runtime.h>
#include <math.h>

#define DEVF __device__ __forceinline__

// ---------------- problem constants ----------------
constexpr int HH = 512, WW = 512, NPIX = HH * WW, NC = 4;
constexpr int DBI = 5, DSP = 2;
constexpr int N_ITER = 10;

constexpr int BI_CAP = 1 << 22;
constexpr int SP_CAP = 1 << 21;
constexpr int BI_MMAX = NPIX * (DBI + 1); // 1,572,864
constexpr int SP_MMAX = NPIX * (DSP + 1); //   786,432
constexpr int BI_PAIRS = BI_MMAX / 2;
constexpr int SP_PAIRS = SP_MMAX / 2;
constexpr unsigned long long KEMPTY = ~0ull;
constexpr unsigned long long M40 = (1ull << 40) - 1;

// ---------------- device scratch ----------------
__device__ unsigned long long g_bi_hk[BI_CAP];   // key (40b) | id<<40 after compact
__device__ unsigned long long g_sp_hk[SP_CAP];
__device__ unsigned long long g_bi_kl[BI_MMAX];
__device__ unsigned long long g_sp_kl[SP_MMAX];
__device__ int   g_bi_off[BI_MMAX];
__device__ int   g_sp_off[SP_MMAX];
__device__ float g_bi_ws[BI_MMAX];
__device__ float g_sp_ws[SP_MMAX];
__device__ __align__(16) int g_bi_bn[(DBI + 1) * BI_MMAX * 2];
__device__ __align__(16) int g_sp_bn[(DSP + 1) * SP_MMAX * 2];
// value buffers: A(0), B(1) ping-pong; C(2) = splat target
__device__ __align__(16) float g_bi_vA[BI_MMAX * NC];
__device__ __align__(16) float g_bi_vB[BI_MMAX * NC];
__device__ __align__(16) float g_bi_vC[BI_MMAX * NC];
__device__ __align__(16) float g_sp_vA[SP_MMAX * NC];
__device__ __align__(16) float g_sp_vB[SP_MMAX * NC];
__device__ __align__(16) float g_sp_vC[SP_MMAX * NC];
__device__ float g_bi_nA[BI_MMAX];
__device__ float g_bi_nB[BI_MMAX];
__device__ float g_sp_nA[SP_MMAX];
__device__ float g_sp_nB[SP_MMAX];
__device__ float g_bi_norm[NPIX];
__device__ float g_sp_norm[NPIX];
__device__ int   g_bi_cnt, g_sp_cnt;

// ---------------- templated accessors ----------------
template<int D> DEVF unsigned long long* HK()  { return D == DBI ? g_bi_hk  : g_sp_hk;  }
template<int D> DEVF unsigned long long* KL()  { return D == DBI ? g_bi_kl  : g_sp_kl;  }
template<int D> DEVF int*   OFFA() { return D == DBI ? g_bi_off : g_sp_off; }
template<int D> DEVF float* WSA()  { return D == DBI ? g_bi_ws  : g_sp_ws;  }
template<int D> DEVF int*   BNA()  { return D == DBI ? g_bi_bn  : g_sp_bn;  }
template<int D> DEVF int*   CNT()  { return D == DBI ? &g_bi_cnt: &g_sp_cnt;}
template<int D> DEVF int    CAPC() { return D == DBI ? BI_CAP   : SP_CAP;   }
template<int D> DEVF int    MMAXC(){ return D == DBI ? BI_MMAX  : SP_MMAX;  }
// key packing: bits per coordinate (bi: 8, sp: 10); bias = half-range
template<int D> DEVF int    KBITS(){ return D == DBI ? 8 : 10; }
template<int D> DEVF int    KBIAS(){ return D == DBI ? 128 : 512; }
template<int D> DEVF unsigned KMASK(){ return D == DBI ? 0xFFu : 0x3FFu; }

template<int D, int C> DEVF float* BUF3(int which) {
    if (C == 1) return D == DBI ? (which ? g_bi_nB : g_bi_nA) : (which ? g_sp_nB : g_sp_nA);
    if (D == DBI) return which == 2 ? g_bi_vC : (which ? g_bi_vB : g_bi_vA);
    return which == 2 ? g_sp_vC : (which ? g_sp_vB : g_sp_vA);
}

// vectorized float4 reduction (sm_90+)
DEVF void red4(float* p, float a, float b, float c, float d) {
    asm volatile("{ .reg .u64 pg; cvta.to.global.u64 pg, %0; "
                 "red.global.add.v4.f32 [pg], {%1,%2,%3,%4}; }"
                 :: "l"(p), "f"(a), "f"(b), "f"(c), "f"(d) : "memory");
}

// ---------------- hash ----------------
DEVF unsigned long long hmix(unsigned long long x) {
    x += 0x9E3779B97F4A7C15ull;
    x = (x ^ (x >> 30)) * 0xBF58476D1CE4E5B9ull;
    x = (x ^ (x >> 27)) * 0x94D049BB133111EBull;
    return x ^ (x >> 31);
}

template<int D>
DEVF int insert_slot(unsigned long long key) {
    const unsigned mask = (unsigned)(CAPC<D>() - 1);
    unsigned long long* hk = HK<D>();
    unsigned h = (unsigned)hmix(key) & mask;
    for (;;) {
        unsigned long long prev = atomicCAS(&hk[h], KEMPTY, key);
        if (prev == KEMPTY || prev == key) return (int)h;
        h = (h + 1) & mask;
    }
}

// post-compact lookup: single 8B random read per probe, id in high bits
template<int D>
DEVF int find_id(unsigned long long key) {
    const unsigned mask = (unsigned)(CAPC<D>() - 1);
    const unsigned long long* hk = HK<D>();
    unsigned h = (unsigned)hmix(key) & mask;
    for (;;) {
        unsigned long long v = hk[h];
        if (v == KEMPTY) return -1;
        if ((v & M40) == key) return (int)(v >> 40);
        h = (h + 1) & mask;
    }
}

// ---------------- kernels ----------------
template<int D>
__global__ void k_reset() {
    int i = blockIdx.x * blockDim.x + threadIdx.x;
    if (i >= CAPC<D>()) return;
    HK<D>()[i] = KEMPTY;
    if (i == 0) *CNT<D>() = 0;
}

template<int D>
__global__ void k_build(const float* __restrict__ x) {
    int n = blockIdx.x * blockDim.x + threadIdx.x;
    if (n >= NPIX) return;
    int py = n / WW, px = n - py * WW;

    float fs[D];
    const double inv_std = sqrt(2.0 / 3.0) * (D + 1);
#pragma unroll
    for (int j = 0; j < D; j++) {
        float f;
        if (D == DBI) {
            if (j == 0)      f = __fdiv_rn((float)px, 80.0f);
            else if (j == 1) f = __fdiv_rn((float)py, 80.0f);
            else             f = __fdiv_rn(x[n * 7 + (6 - j)], 0.0625f);
        } else {
            f = __fdiv_rn((float)(j == 0 ? px : py), 3.0f);
        }
        float sc = (float)(1.0 / sqrt((j + 2.0) * (j + 1.0)) * inv_std);
        fs[j] = __fmul_rn(f, sc);
    }

    float elev[D + 1];
#pragma unroll
    for (int i = 0; i <= D; i++) {
        float s = 0.0f;
#pragma unroll
        for (int j = 0; j < D; j++) {
            float e = (i == 0) ? 1.0f : ((j == i - 1) ? -(float)i : (j >= i ? 1.0f : 0.0f));
            s = __fadd_rn(s, __fmul_rn(e, fs[j]));
        }
        elev[i] = s;
    }

    const float downf = __fdiv_rn(1.0f, (float)(D + 1));
    const float upf = (float)(D + 1);

    float rem0[D + 1], diff[D + 1];
    int   rnk[D + 1];
#pragma unroll
    for (int k = 0; k <= D; k++) {
        float v   = __fmul_rn(elev[k], downf);
        float upr = __fmul_rn(ceilf(v),  upf);
        float dnr = __fmul_rn(floorf(v), upf);
        rem0[k] = (__fsub_rn(upr, elev[k]) < __fsub_rn(elev[k], dnr)) ? upr : dnr;
    }
    float ssum = 0.0f;
#pragma unroll
    for (int k = 0; k <= D; k++) ssum = __fadd_rn(ssum, rem0[k]);
    int s = (int)__fmul_rn(ssum, downf);

#pragma unroll
    for (int k = 0; k <= D; k++) diff[k] = __fsub_rn(elev[k], rem0[k]);
#pragma unroll
    for (int k = 0; k <= D; k++) {
        int r = s;
#pragma unroll
        for (int j = 0; j <= D; j++) {
            if (j > k)      r += (diff[k] <  diff[j]);
            else if (j < k) r += (diff[j] >= diff[k]);
        }
        rnk[k] = r;
    }
#pragma unroll
    for (int k = 0; k <= D; k++) {
        if (rnk[k] < 0)      { rnk[k] += D + 1; rem0[k] = __fadd_rn(rem0[k], upf); }
        else if (rnk[k] > D) { rnk[k] -= D + 1; rem0[k] = __fsub_rn(rem0[k], upf); }
    }

    float b[D + 2];
#pragma unroll
    for (int k = 0; k < D + 2; k++) b[k] = 0.0f;
#pragma unroll
    for (int k = 0; k <= D; k++) {
        float vs = __fmul_rn(__fsub_rn(elev[k], rem0[k]), downf);
        int idx = D - rnk[k];
        b[idx]     = __fadd_rn(b[idx], vs);
        b[idx + 1] = __fsub_rn(b[idx + 1], vs);
    }
    b[0] = __fadd_rn(b[0], __fadd_rn(1.0f, b[D + 1]));

    int remi[D + 1];
#pragma unroll
    for (int k = 0; k <= D; k++) remi[k] = (int)rem0[k];

#pragma unroll
    for (int m = 0; m <= D; m++) {
        unsigned long long key = 0ull;
#pragma unroll
        for (int j = 0; j < D; j++) {
            int r  = rnk[j];
            int cm = (r < D + 1 - m) ? m : m - (D + 1);
            int c  = remi[j] + cm;
            key |= ((unsigned long long)((unsigned)(c + KBIAS<D>()) & KMASK<D>())) << (KBITS<D>() * j);
        }
        int slot = insert_slot<D>(key);
        OFFA<D>()[n * (D + 1) + m] = slot;
        WSA<D>()[n * (D + 1) + m]  = b[m];
    }
}

template<int D>
__global__ void k_compact() {
    int i = blockIdx.x * blockDim.x + threadIdx.x;
    if (i >= CAPC<D>()) return;
    unsigned long long k = HK<D>()[i];
    if (k != KEMPTY) {
        int id = atomicAdd(CNT<D>(), 1);
        HK<D>()[i] = k | ((unsigned long long)id << 40);
        KL<D>()[id] = k;
    }
}

template<int D>
__global__ void k_fixoff() {
    int i = blockIdx.x * blockDim.x + threadIdx.x;
    if (i >= NPIX * (D + 1)) return;
    OFFA<D>()[i] = (int)(HK<D>()[OFFA<D>()[i]] >> 40);
}

template<int D>
__global__ void k_neigh() {
    int i = blockIdx.x * blockDim.x + threadIdx.x;
    if (i >= *CNT<D>()) return;
    unsigned long long key = KL<D>()[i];
    int c[D];
#pragma unroll
    for (int j = 0; j < D; j++) c[j] = (int)((key >> (KBITS<D>() * j)) & KMASK<D>()) - KBIAS<D>();
#pragma unroll
    for (int j = 0; j <= D; j++) {
        unsigned long long k1 = 0ull, k2 = 0ull;
#pragma unroll
        for (int t = 0; t < D; t++) {
            int add = (j < D && t == j) ? (D + 1) : 0;
            int c1 = c[t] - 1 + add;
            int c2 = c[t] + 1 - add;
            k1 |= ((unsigned long long)((unsigned)(c1 + KBIAS<D>()) & KMASK<D>())) << (KBITS<D>() * t);
            k2 |= ((unsigned long long)((unsigned)(c2 + KBIAS<D>()) & KMASK<D>())) << (KBITS<D>() * t);
        }
        ((int2*)BNA<D>())[j * MMAXC<D>() + i] = make_int2(find_id<D>(k1), find_id<D>(k2));
    }
}

// clear norm splat buffers (nA for both lattices)
__global__ void k_clearN() {
    int i = blockIdx.x * blockDim.x + threadIdx.x;
    if (i < BI_MMAX) { if (i < g_bi_cnt) g_bi_nA[i] = 0.0f; }
    else { int k = i - BI_MMAX; if (k < g_sp_cnt) g_sp_nA[k] = 0.0f; }
}

// one-time clear of splat (C) buffers, float4 stores
__global__ void k_clearC() {
    int i = blockIdx.x * blockDim.x + threadIdx.x;
    if (i < BI_MMAX) { if (i < g_bi_cnt) ((float4*)g_bi_vC)[i] = make_float4(0, 0, 0, 0); }
    else { int k = i - BI_MMAX; if (k < g_sp_cnt) ((float4*)g_sp_vC)[k] = make_float4(0, 0, 0, 0); }
}

// norm splat: both lattices in one kernel
__global__ void k_splatN() {
    int i = blockIdx.x * blockDim.x + threadIdx.x;
    if (i < BI_MMAX) atomicAdd(&g_bi_nA[g_bi_off[i]], g_bi_ws[i]);
    else { int k = i - BI_MMAX; if (k < SP_MMAX) atomicAdd(&g_sp_nA[g_sp_off[k]], g_sp_ws[k]); }
}

// blur a pair of points (i, i+1), i even; optional clear of C buffer
template<int D, int C, bool CLR>
DEVF void blur_pair(int i, int axis, int inb, int outb) {
    int cnt = *CNT<D>();
    if (i >= cnt) return;
    const int2* bnA = ((const int2*)BNA<D>()) + axis * MMAXC<D>();
    int4 nbp = *(const int4*)(bnA + i);          // neighbors of i (x,y) and i+1 (z,w)
    bool two = (i + 1 < cnt);
    if (C == 1) {
        const float* in = BUF3<D, 1>(inb);
        float* outp = BUF3<D, 1>(outb);
        float s0 = 0.0f;
        if (nbp.x >= 0) s0 += in[nbp.x];
        if (nbp.y >= 0) s0 += in[nbp.y];
        outp[i] = in[i] + 0.5f * s0;
        if (two) {
            float s1 = 0.0f;
            if (nbp.z >= 0) s1 += in[nbp.z];
            if (nbp.w >= 0) s1 += in[nbp.w];
            outp[i + 1] = in[i + 1] + 0.5f * s1;
        }
    } else {
        const float4* in = (const float4*)BUF3<D, C>(inb);
        float4* outp = (float4*)BUF3<D, C>(outb);
        float4 v0 = in[i];
        float4 v1 = two ? in[i + 1] : make_float4(0, 0, 0, 0);
        float4 a0 = make_float4(0, 0, 0, 0), b0 = a0, a1 = a0, b1 = a0;
        if (nbp.x >= 0) a0 = in[nbp.x];
        if (nbp.y >= 0) b0 = in[nbp.y];
        if (two && nbp.z >= 0) a1 = in[nbp.z];
        if (two && nbp.w >= 0) b1 = in[nbp.w];
        v0.x += 0.5f * (a0.x + b0.x); v0.y += 0.5f * (a0.y + b0.y);
        v0.z += 0.5f * (a0.z + b0.z); v0.w += 0.5f * (a0.w + b0.w);
        outp[i] = v0;
        if (two) {
            v1.x += 0.5f * (a1.x + b1.x); v1.y += 0.5f * (a1.y + b1.y);
            v1.z += 0.5f * (a1.z + b1.z); v1.w += 0.5f * (a1.w + b1.w);
            outp[i + 1] = v1;
        }
        if (CLR) {
            float4* cb = (float4*)BUF3<D, C>(2);
            cb[i] = make_float4(0, 0, 0, 0);
            if (two) cb[i + 1] = make_float4(0, 0, 0, 0);
        }
    }
}

// combined blur: bi pairs first, then sp pairs (when axis <= DSP)
template<int C, bool CLR>
__global__ void k_blur(int axis, int inb, int outb) {
    int t = blockIdx.x * blockDim.x + threadIdx.x;
    if (t < BI_PAIRS) {
        blur_pair<DBI, C, CLR>(2 * t, axis, inb, outb);
    } else {
        int k = t - BI_PAIRS;
        if (k < SP_PAIRS) blur_pair<DSP, C, CLR>(2 * k, axis, inb, outb);
    }
}

// slice of norm filters (bi final in nA, sp final in nB)
__global__ void k_sliceN() {
    int n = blockIdx.x * blockDim.x + threadIdx.x;
    if (n >= NPIX) return;
    float sb = 0.0f, ss = 0.0f;
#pragma unroll
    for (int m = 0; m <= DBI; m++)
        sb += g_bi_ws[n * (DBI + 1) + m] * g_bi_nA[g_bi_off[n * (DBI + 1) + m]];
#pragma unroll
    for (int m = 0; m <= DSP; m++)
        ss += g_sp_ws[n * (DSP + 1) + m] * g_sp_nB[g_sp_off[n * (DSP + 1) + m]];
    g_bi_norm[n] = sb * (32.0f / 33.0f);
    g_sp_norm[n] = ss * 0.8f;
}

DEVF void splat_q(int n, float q0, float q1, float q2, float q3) {
#pragma unroll
    for (int m = 0; m <= DBI; m++) {
        int id  = g_bi_off[n * (DBI + 1) + m];
        float w = g_bi_ws[n * (DBI + 1) + m];
        red4(&g_bi_vC[id * 4], w * q0, w * q1, w * q2, w * q3);
    }
#pragma unroll
    for (int m = 0; m <= DSP; m++) {
        int id  = g_sp_off[n * (DSP + 1) + m];
        float w = g_sp_ws[n * (DSP + 1) + m];
        red4(&g_sp_vC[id * 4], w * q0, w * q1, w * q2, w * q3);
    }
}

__global__ void k_initQ(const float* __restrict__ logits) {
    int n = blockIdx.x * blockDim.x + threadIdx.x;
    if (n >= NPIX) return;
    float4 lg = ((const float4*)logits)[n];
    float mx = fmaxf(fmaxf(lg.x, lg.y), fmaxf(lg.z, lg.w));
    float e0 = expf(lg.x - mx), e1 = expf(lg.y - mx), e2 = expf(lg.z - mx), e3 = expf(lg.w - mx);
    float inv = 1.0f / (e0 + e1 + e2 + e3);
    splat_q(n, e0 * inv, e1 * inv, e2 * inv, e3 * inv);
}

template<bool LAST>
__global__ void k_update(const float* __restrict__ logits, float* __restrict__ out) {
    int n = blockIdx.x * blockDim.x + threadIdx.x;
    if (n >= NPIX) return;
    const float4* vb = (const float4*)g_bi_vA; // bi after 6 passes (C->B->A->B->A->B->A)
    const float4* vs = (const float4*)g_sp_vB; // sp after 3 passes (C->B->A->B)
    float ab0 = 0, ab1 = 0, ab2 = 0, ab3 = 0;
    float as0 = 0, as1 = 0, as2 = 0, as3 = 0;
#pragma unroll
    for (int m = 0; m <= DBI; m++) {
        int id  = g_bi_off[n * (DBI + 1) + m];
        float w = g_bi_ws[n * (DBI + 1) + m];
        float4 t = vb[id];
        ab0 += w * t.x; ab1 += w * t.y; ab2 += w * t.z; ab3 += w * t.w;
    }
#pragma unroll
    for (int m = 0; m <= DSP; m++) {
        int id  = g_sp_off[n * (DSP + 1) + m];
        float w = g_sp_ws[n * (DSP + 1) + m];
        float4 t = vs[id];
        as0 += w * t.x; as1 += w * t.y; as2 += w * t.z; as3 += w * t.w;
    }
    float fbi = 10.0f * (32.0f / 33.0f) / (g_bi_norm[n] + 1e-20f);
    float fsp = 3.0f * 0.8f / (g_sp_norm[n] + 1e-20f);
    float4 lg = ((const float4*)logits)[n];
    float a0 = lg.x + fbi * ab0 + fsp * as0;
    float a1 = lg.y + fbi * ab1 + fsp * as1;
    float a2 = lg.z + fbi * ab2 + fsp * as2;
    float a3 = lg.w + fbi * ab3 + fsp * as3;
    float mx = fmaxf(fmaxf(a0, a1), fmaxf(a2, a3));
    float e0 = expf(a0 - mx), e1 = expf(a1 - mx), e2 = expf(a2 - mx), e3 = expf(a3 - mx);
    float inv = 1.0f / (e0 + e1 + e2 + e3);
    float q0 = e0 * inv, q1 = e1 * inv, q2 = e2 * inv, q3 = e3 * inv;
    if (LAST) {
        ((float4*)out)[n] = make_float4(q0, q1, q2, q3);
    } else {
        splat_q(n, q0, q1, q2, q3);
    }
}

// ---------------- launch ----------------
extern "C" void kernel_launch(void* const* d_in, const int* in_sizes, int n_in,
                              void* d_out, int out_size) {
    (void)in_sizes; (void)n_in; (void)out_size;
    const float* x      = (const float*)d_in[0];
    const float* logits = (const float*)d_in[1];
    float* out = (float*)d_out;

    const int B = 256;
    auto g = [](long n) { return (unsigned)((n + 255) / 256); };
    const unsigned G_BOTH   = g(BI_MMAX + SP_MMAX);
    const unsigned G_BI     = g(BI_MMAX);
    const unsigned G_PAIRS  = g(BI_PAIRS + SP_PAIRS);
    const unsigned G_PAIRSB = g(BI_PAIRS);
    const unsigned G_PIX    = g(NPIX);

    // ---- lattice construction ----
    k_reset<DBI><<<g(BI_CAP), B>>>();
    k_reset<DSP><<<g(SP_CAP), B>>>();
    k_build<DBI><<<G_PIX, B>>>(x);
    k_build<DSP><<<G_PIX, B>>>(x);
    k_compact<DBI><<<g(BI_CAP), B>>>();
    k_compact<DSP><<<g(SP_CAP), B>>>();
    k_fixoff<DBI><<<G_BI, B>>>();
    k_fixoff<DSP><<<g(SP_MMAX), B>>>();
    k_neigh<DBI><<<G_BI, B>>>();
    k_neigh<DSP><<<g(SP_MMAX), B>>>();

    // ---- normalization filters ----
    k_clearN<<<G_BOTH, B>>>();
    k_splatN<<<G_BOTH, B>>>();
    for (int j = 0; j <= DBI; j++) {
        unsigned grd = (j <= DSP) ? G_PAIRS : G_PAIRSB;
        k_blur<1, false><<<grd, B>>>(j, j & 1, (j & 1) ^ 1);
    }
    k_sliceN<<<G_PIX, B>>>();

    // ---- mean-field iterations ----
    k_clearC<<<G_BOTH, B>>>();
    k_initQ<<<G_PIX, B>>>(logits);
    for (int it = 0; it < N_ITER; it++) {
        for (int j = 0; j <= DBI; j++) {
            int inb  = (j == 0) ? 2 : (j & 1);
            int outb = (j & 1) ^ 1;
            unsigned grd = (j <= DSP) ? G_PAIRS : G_PAIRSB;
            if (j == 1)
                k_blur<NC, true><<<grd, B>>>(j, inb, outb);   // clears C inline
            else
                k_blur<NC, false><<<grd, B>>>(j, inb, outb);
        }
        if (it == N_ITER - 1)
            k_update<true><<<G_PIX, B>>>(logits, out);
        else
            k_update<false><<<G_PIX, B>>>(logits, out);
    }
}